// round 15
// baseline (speedup 1.0000x reference)
#include <cuda_runtime.h>
#include <cuda_bf16.h>
#include <math_constants.h>
#include <cstdint>

// Tropical (max-plus) matmul via log-sum-exp + bf16 mma.sync GEMM.
//   y[b,i] = mx_b + T*( ln( sum_j e^{(x_bj-mx_b)/T + CA} * e^{W_ij/T} ) - CA )
// T = 0.005, CA = 20.
//
// R11 = R10 with the smem stride bug fixed: SROW=40 bf16 (80 B, 16B-aligned,
// conflict-free). Two kernels: unique-work prep, then 64x64-tile GEMM at
// 256 CTAs (2 CTAs/SM), PDL overlap.

#define KDIM 512
#define NDIM 512
#define MAXB 2048
#define T_VAL 0.005f
#define CA_SHIFT 20.0f
#define C1_X 288.539008f   // (1/T)*log2(e)
#define C0_X 28.8539008f   // CA*log2(e)

__device__ float g_mx[MAXB];
__device__ __align__(16) __nv_bfloat16 g_Ax[MAXB * KDIM];
__device__ __align__(16) __nv_bfloat16 g_Bw[NDIM * KDIM];

__device__ __forceinline__ float ex2_approx(float t)
{ float r; asm("ex2.approx.f32 %0, %1;" : "=f"(r) : "f"(t)); return r; }

__device__ __forceinline__ float fast_ln(float v)
{
    int   iv = __float_as_int(v);
    float e  = (float)((iv >> 23) - 127);
    float m  = __int_as_float((iv & 0x7FFFFF) | 0x3F800000);
    float p  = -0.0565708f;
    p = fmaf(p, m,  0.4471796f);
    p = fmaf(p, m, -1.4699568f);
    p = fmaf(p, m,  2.8212026f);
    p = fmaf(p, m, -1.7417939f);
    return fmaf(e, 0.6931472f, p);
}

// ---------------- prep kernel: one warp per row, unique work only ----------

__global__ __launch_bounds__(256, 4) void prep_kernel(const float* __restrict__ x,
                                                      const float* __restrict__ w,
                                                      int Brows)
{
    const int gr   = blockIdx.x * 8 + (threadIdx.x >> 5);
    const int lane = threadIdx.x & 31;

    if (gr < Brows) {
        const float4* xr = (const float4*)(x + (size_t)gr * KDIM);
        float4 v[4];
        #pragma unroll
        for (int p = 0; p < 4; p++) v[p] = xr[lane + 32 * p];

        float m = -CUDART_INF_F;
        #pragma unroll
        for (int p = 0; p < 4; p++)
            m = fmaxf(m, fmaxf(fmaxf(v[p].x, v[p].y), fmaxf(v[p].z, v[p].w)));
        #pragma unroll
        for (int o = 16; o; o >>= 1) m = fmaxf(m, __shfl_xor_sync(0xffffffffu, m, o));
        if (lane == 0) g_mx[gr] = m;

        const float base = fmaf(-m, C1_X, C0_X);
        __nv_bfloat162* orow = (__nv_bfloat162*)(g_Ax + (size_t)gr * KDIM);
        #pragma unroll
        for (int p = 0; p < 4; p++) {
            float4 t = v[p];
            float e0 = ex2_approx(fmaf(t.x, C1_X, base));
            float e1 = ex2_approx(fmaf(t.y, C1_X, base));
            float e2 = ex2_approx(fmaf(t.z, C1_X, base));
            float e3 = ex2_approx(fmaf(t.w, C1_X, base));
            orow[(lane + 32 * p) * 2 + 0] = __floats2bfloat162_rn(e0, e1);
            orow[(lane + 32 * p) * 2 + 1] = __floats2bfloat162_rn(e2, e3);
        }
    } else {
        const int row = gr - Brows;
        if (row >= NDIM) return;
        const float4* wr = (const float4*)(w + (size_t)row * KDIM);
        __nv_bfloat162* orow = (__nv_bfloat162*)(g_Bw + (size_t)row * KDIM);
        #pragma unroll
        for (int p = 0; p < 4; p++) {
            float4 t = wr[lane + 32 * p];
            float e0 = ex2_approx(t.x * C1_X);
            float e1 = ex2_approx(t.y * C1_X);
            float e2 = ex2_approx(t.z * C1_X);
            float e3 = ex2_approx(t.w * C1_X);
            orow[(lane + 32 * p) * 2 + 0] = __floats2bfloat162_rn(e0, e1);
            orow[(lane + 32 * p) * 2 + 1] = __floats2bfloat162_rn(e2, e3);
        }
    }
}

// ---------------- GEMM: 64x64 tiles, 256 CTAs, 2 CTAs/SM ----------------

__device__ __forceinline__ void ldsm_x4(uint32_t& r0, uint32_t& r1,
                                        uint32_t& r2, uint32_t& r3, const void* p)
{
    uint32_t a = (uint32_t)__cvta_generic_to_shared(p);
    asm volatile("ldmatrix.sync.aligned.m8n8.x4.shared.b16 {%0,%1,%2,%3}, [%4];"
                 : "=r"(r0), "=r"(r1), "=r"(r2), "=r"(r3) : "r"(a));
}

__device__ __forceinline__ void mma_bf16(float* c, const uint32_t* a, uint32_t b0, uint32_t b1)
{
    asm volatile(
        "mma.sync.aligned.m16n8k16.row.col.f32.bf16.bf16.f32 "
        "{%0,%1,%2,%3},{%4,%5,%6,%7},{%8,%9},{%0,%1,%2,%3};"
        : "+f"(c[0]), "+f"(c[1]), "+f"(c[2]), "+f"(c[3])
        : "r"(a[0]), "r"(a[1]), "r"(a[2]), "r"(a[3]), "r"(b0), "r"(b1));
}

#define BK 32
#define NKIT (KDIM / BK)   // 16
#define SROW 40            // 80 B row stride: 16B-aligned, conflict-free

struct Frag { uint32_t a[2][4]; uint32_t b[4]; };

__global__ __launch_bounds__(256)
void lse_gemm_kernel(float* __restrict__ out)
{
    __shared__ __align__(16) __nv_bfloat16 As[2][64][SROW];   // 10.2 KB
    __shared__ __align__(16) __nv_bfloat16 Bs[2][64][SROW];   // 10.2 KB

    const int tid  = threadIdx.x;
    const int warp = tid >> 5, lane = tid & 31;
    const int wm = warp & 1, wn = warp >> 1;    // 2x4 warp grid, 32x16 warp tile
    const int bm = blockIdx.y * 64, bn = blockIdx.x * 64;

    const int arow = tid >> 2;          // 0..63
    const int ac   = tid & 3;           // 16B chunk (8 bf16)
    const int lr   = lane & 15;
    const int lh   = (lane >> 4) * 8;

    float acc[2][2][4];
    #pragma unroll
    for (int i = 0; i < 2; i++)
        #pragma unroll
        for (int j = 0; j < 2; j++)
            #pragma unroll
            for (int k = 0; k < 4; k++) acc[i][j][k] = 0.f;

    // PDL: overlap setup with prep drain; block before first dependent load.
    cudaGridDependencySynchronize();

    const uint4* ag = (const uint4*)(g_Ax + (size_t)(bm + arow) * KDIM) + ac;
    const uint4* bg = (const uint4*)(g_Bw + (size_t)(bn + arow) * KDIM) + ac;

    // prologue: tile 0
    uint4 pa = ag[0], pb = bg[0];
    *(uint4*)&As[0][arow][ac * 8] = pa;
    *(uint4*)&Bs[0][arow][ac * 8] = pb;
    __syncthreads();

    for (int it = 0; it < NKIT; it++) {
        const int cur = it & 1;

        if (it + 1 < NKIT) {                 // gmem prefetch for tile it+1
            pa = ag[(it + 1) * (BK / 8)];
            pb = bg[(it + 1) * (BK / 8)];
        }

        Frag fr[2];
        #pragma unroll
        for (int mt = 0; mt < 2; mt++)
            ldsm_x4(fr[0].a[mt][0], fr[0].a[mt][1], fr[0].a[mt][2], fr[0].a[mt][3],
                    &As[cur][wm * 32 + mt * 16 + lr][lh]);
        ldsm_x4(fr[0].b[0], fr[0].b[1], fr[0].b[2], fr[0].b[3],
                &Bs[cur][wn * 16 + lr][lh]);

        #pragma unroll
        for (int kk = 0; kk < BK / 16; kk++) {
            const int cf = kk & 1, nf = cf ^ 1;
            if (kk + 1 < BK / 16) {
                const int ko = (kk + 1) * 16 + lh;
                #pragma unroll
                for (int mt = 0; mt < 2; mt++)
                    ldsm_x4(fr[nf].a[mt][0], fr[nf].a[mt][1], fr[nf].a[mt][2], fr[nf].a[mt][3],
                            &As[cur][wm * 32 + mt * 16 + lr][ko]);
                ldsm_x4(fr[nf].b[0], fr[nf].b[1], fr[nf].b[2], fr[nf].b[3],
                        &Bs[cur][wn * 16 + lr][ko]);
            }
            #pragma unroll
            for (int mt = 0; mt < 2; mt++) {
                mma_bf16(acc[mt][0], fr[cf].a[mt], fr[cf].b[0], fr[cf].b[2]);
                mma_bf16(acc[mt][1], fr[cf].a[mt], fr[cf].b[1], fr[cf].b[3]);
            }
        }

        if (it + 1 < NKIT) {
            const int nxt = cur ^ 1;
            *(uint4*)&As[nxt][arow][ac * 8] = pa;
            *(uint4*)&Bs[nxt][arow][ac * 8] = pb;
            __syncthreads();
        }
    }

    // ---- epilogue: ln -> smem stage -> coalesced float4 stores ----
    const int g = lane >> 2, t4 = lane & 3;
    float mx0[2], mx1[2];
    #pragma unroll
    for (int mt = 0; mt < 2; mt++) {
        mx0[mt] = __ldg(&g_mx[bm + wm * 32 + mt * 16 + g]);
        mx1[mt] = __ldg(&g_mx[bm + wm * 32 + mt * 16 + g + 8]);
    }
    __syncthreads();                        // all smem reads done before aliasing
    float* stg = (float*)&As[0][0][0];      // 64 rows x 68 floats = 17.4 KB

    #pragma unroll
    for (int mt = 0; mt < 2; mt++) {
        const int r0 = wm * 32 + mt * 16 + g;
        #pragma unroll
        for (int nt = 0; nt < 2; nt++) {
            const int c0 = wn * 16 + nt * 8 + 2 * t4;
            stg[r0 * 68 + c0]           = mx0[mt] + T_VAL * (fast_ln(acc[mt][nt][0]) - CA_SHIFT);
            stg[r0 * 68 + c0 + 1]       = mx0[mt] + T_VAL * (fast_ln(acc[mt][nt][1]) - CA_SHIFT);
            stg[(r0 + 8) * 68 + c0]     = mx1[mt] + T_VAL * (fast_ln(acc[mt][nt][2]) - CA_SHIFT);
            stg[(r0 + 8) * 68 + c0 + 1] = mx1[mt] + T_VAL * (fast_ln(acc[mt][nt][3]) - CA_SHIFT);
        }
    }
    __syncthreads();

    #pragma unroll
    for (int s = 0; s < 4; s++) {           // 1024 float4 chunks / 256 threads
        const int i = tid + s * 256;
        const int r = i >> 4, c4 = i & 15;
        float4 v = *(float4*)&stg[r * 68 + c4 * 4];
        *(float4*)&out[(size_t)(bm + r) * NDIM + bn + c4 * 4] = v;
    }
}

// ---------------- launch ----------------

extern "C" void kernel_launch(void* const* d_in, const int* in_sizes, int n_in,
                              void* d_out, int out_size)
{
    const float* x = (const float*)d_in[0];
    const float* W = (const float*)d_in[1];
    int nx = in_sizes[0], nw = in_sizes[1];
    if (nx == NDIM * KDIM && nw != NDIM * KDIM) {   // input-order safety
        const float* t = x; x = W; W = t;
        int ts = nx; nx = nw; nw = ts;
    }
    const int B = nx / KDIM;   // 2048

    const int prep_rows = B + NDIM;                   // 2560
    prep_kernel<<<(prep_rows + 7) / 8, 256>>>(x, W, B);

    cudaLaunchConfig_t cfg = {};
    cfg.gridDim  = dim3(NDIM / 64, B / 64, 1);        // (8,32) = 256 CTAs
    cfg.blockDim = dim3(256, 1, 1);
    cfg.stream   = 0;
    cudaLaunchAttribute attr[1];
    attr[0].id = cudaLaunchAttributeProgrammaticStreamSerialization;
    attr[0].val.programmaticStreamSerializationAllowed = 1;
    cfg.attrs = attr;
    cfg.numAttrs = 1;
    cudaError_t e = cudaLaunchKernelEx(&cfg, lse_gemm_kernel, (float*)d_out);
    if (e != cudaSuccess) {
        dim3 grid(NDIM / 64, B / 64);
        lse_gemm_kernel<<<grid, 256>>>((float*)d_out);
    }
}

// round 16
// speedup vs baseline: 1.1358x; 1.1358x over previous
#include <cuda_runtime.h>
#include <cuda_bf16.h>
#include <math_constants.h>
#include <cstdint>

// Tropical (max-plus) matmul via log-sum-exp + bf16 mma.sync GEMM.
//   y[b,i] = mx_b + T*( ln( sum_j e^{(x_bj-mx_b)/T + CA} * e^{W_ij/T} ) - CA )
// T = 0.005, CA = 20.
//
// R12: split-K GEMM. 128x64 CTA tile, 512 threads: warps 0-7 accumulate
// K[0:256], warps 8-15 K[256:512] (identical 4x2 warp grids, 32x32 tiles),
// partial sums combined through smem. 4 BK=128 slab iterations, 4 barriers.

#define KDIM 512
#define NDIM 512
#define MAXB 2048
#define T_VAL 0.005f
#define CA_SHIFT 20.0f
#define C1_X 288.539008f   // (1/T)*log2(e)
#define C0_X 28.8539008f   // CA*log2(e)

__device__ float g_mx[MAXB];
__device__ __align__(16) __nv_bfloat16 g_Ax[MAXB * KDIM];
__device__ __align__(16) __nv_bfloat16 g_Bw[NDIM * KDIM];

__device__ __forceinline__ float ex2_approx(float t)
{ float r; asm("ex2.approx.f32 %0, %1;" : "=f"(r) : "f"(t)); return r; }

__device__ __forceinline__ float fast_ln(float v)
{
    int   iv = __float_as_int(v);
    float e  = (float)((iv >> 23) - 127);
    float m  = __int_as_float((iv & 0x7FFFFF) | 0x3F800000);
    float p  = -0.0565708f;
    p = fmaf(p, m,  0.4471796f);
    p = fmaf(p, m, -1.4699568f);
    p = fmaf(p, m,  2.8212026f);
    p = fmaf(p, m, -1.7417939f);
    return fmaf(e, 0.6931472f, p);
}

// ---------------- prep kernel: one warp per row, unique work only ----------

__global__ __launch_bounds__(256, 4) void prep_kernel(const float* __restrict__ x,
                                                      const float* __restrict__ w,
                                                      int Brows)
{
    const int gr   = blockIdx.x * 8 + (threadIdx.x >> 5);
    const int lane = threadIdx.x & 31;

    if (gr < Brows) {
        const float4* xr = (const float4*)(x + (size_t)gr * KDIM);
        float4 v[4];
        #pragma unroll
        for (int p = 0; p < 4; p++) v[p] = xr[lane + 32 * p];

        float m = -CUDART_INF_F;
        #pragma unroll
        for (int p = 0; p < 4; p++)
            m = fmaxf(m, fmaxf(fmaxf(v[p].x, v[p].y), fmaxf(v[p].z, v[p].w)));
        #pragma unroll
        for (int o = 16; o; o >>= 1) m = fmaxf(m, __shfl_xor_sync(0xffffffffu, m, o));
        if (lane == 0) g_mx[gr] = m;

        const float base = fmaf(-m, C1_X, C0_X);
        __nv_bfloat162* orow = (__nv_bfloat162*)(g_Ax + (size_t)gr * KDIM);
        #pragma unroll
        for (int p = 0; p < 4; p++) {
            float4 t = v[p];
            float e0 = ex2_approx(fmaf(t.x, C1_X, base));
            float e1 = ex2_approx(fmaf(t.y, C1_X, base));
            float e2 = ex2_approx(fmaf(t.z, C1_X, base));
            float e3 = ex2_approx(fmaf(t.w, C1_X, base));
            orow[(lane + 32 * p) * 2 + 0] = __floats2bfloat162_rn(e0, e1);
            orow[(lane + 32 * p) * 2 + 1] = __floats2bfloat162_rn(e2, e3);
        }
    } else {
        const int row = gr - Brows;
        if (row >= NDIM) return;
        const float4* wr = (const float4*)(w + (size_t)row * KDIM);
        __nv_bfloat162* orow = (__nv_bfloat162*)(g_Bw + (size_t)row * KDIM);
        #pragma unroll
        for (int p = 0; p < 4; p++) {
            float4 t = wr[lane + 32 * p];
            float e0 = ex2_approx(t.x * C1_X);
            float e1 = ex2_approx(t.y * C1_X);
            float e2 = ex2_approx(t.z * C1_X);
            float e3 = ex2_approx(t.w * C1_X);
            orow[(lane + 32 * p) * 2 + 0] = __floats2bfloat162_rn(e0, e1);
            orow[(lane + 32 * p) * 2 + 1] = __floats2bfloat162_rn(e2, e3);
        }
    }
}

// ---------------- split-K GEMM ----------------

__device__ __forceinline__ void ldsm_x4(uint32_t& r0, uint32_t& r1,
                                        uint32_t& r2, uint32_t& r3, uint32_t a)
{
    asm volatile("ldmatrix.sync.aligned.m8n8.x4.shared.b16 {%0,%1,%2,%3}, [%4];"
                 : "=r"(r0), "=r"(r1), "=r"(r2), "=r"(r3) : "r"(a));
}

__device__ __forceinline__ void mma_bf16(float* c, const uint32_t* a, uint32_t b0, uint32_t b1)
{
    asm volatile(
        "mma.sync.aligned.m16n8k16.row.col.f32.bf16.bf16.f32 "
        "{%0,%1,%2,%3},{%4,%5,%6,%7},{%8,%9},{%0,%1,%2,%3};"
        : "+f"(c[0]), "+f"(c[1]), "+f"(c[2]), "+f"(c[3])
        : "r"(a[0]), "r"(a[1]), "r"(a[2]), "r"(a[3]), "r"(b0), "r"(b1));
}

#define BKF 128            // slab width (cols) per iteration; halves take 64 each
#define NIT (KDIM / BKF)   // 4
#define RB  272            // bytes per smem row: 136 bf16, 16B-aligned, 68 words ≡ 4 mod 32

// dynamic smem map
#define SM_AS 0                       // A: 2 bufs x 128 rows x 272 B = 69632
#define SM_BS 69632                   // B: 2 bufs x  64 rows x 272 B = 34816
#define SM_EX 69632                   // exchange (reuses B after mainloop): 8*32*32*4 = 32768
#define SM_TOT 104448

struct Frag { uint32_t a[2][4]; uint32_t b0[4]; uint32_t b1[4]; };

__global__ __launch_bounds__(512)
void lse_gemm_kernel(float* __restrict__ out)
{
    extern __shared__ __align__(16) unsigned char sm[];

    const int tid  = threadIdx.x;
    const int warp = tid >> 5, lane = tid & 31;
    const int half = warp >> 3;           // k-split group
    const int wg   = warp & 7;            // 4x2 grid within group
    const int wm   = wg & 3, wn = wg >> 2;
    const int bm   = blockIdx.y * 128, bn = blockIdx.x * 64;

    // loader mapping
    const int arow = tid >> 2, ac = tid & 3;     // A: 128 rows x 16 chunks (4/thread)
    const int brow = tid >> 3, bc = tid & 7;     // B:  64 rows x 16 chunks (2/thread)
    const int lr   = lane & 15;
    const int lh   = (lane >> 4) * 8;

    float acc[2][4][4];
    #pragma unroll
    for (int i = 0; i < 2; i++)
        #pragma unroll
        for (int j = 0; j < 4; j++)
            #pragma unroll
            for (int k = 0; k < 4; k++) acc[i][j][k] = 0.f;

    // PDL: overlap setup with prep drain; block before first dependent load.
    cudaGridDependencySynchronize();

    const uint4* ag = (const uint4*)(g_Ax + (size_t)(bm + arow) * KDIM);
    const uint4* bg = (const uint4*)(g_Bw + (size_t)(bn + brow) * KDIM);

    // LDSM base addresses (buf 0); add buf offset in-loop
    uint32_t abase[2], b0base, b1base;
    #pragma unroll
    for (int mt = 0; mt < 2; mt++)
        abase[mt] = (uint32_t)__cvta_generic_to_shared(
            sm + SM_AS + (wm * 32 + mt * 16 + lr) * RB + half * 128 + lh * 2);
    b0base = (uint32_t)__cvta_generic_to_shared(
        sm + SM_BS + (wn * 32 + lr) * RB + half * 128 + lh * 2);
    b1base = (uint32_t)__cvta_generic_to_shared(
        sm + SM_BS + (wn * 32 + 16 + lr) * RB + half * 128 + lh * 2);

    // prologue: slab 0 -> buf 0
    uint4 pa[4], pb[2];
    #pragma unroll
    for (int j = 0; j < 4; j++) pa[j] = ag[ac + 4 * j];
    #pragma unroll
    for (int j = 0; j < 2; j++) pb[j] = bg[bc + 8 * j];
    #pragma unroll
    for (int j = 0; j < 4; j++)
        *(uint4*)(sm + SM_AS + arow * RB + (ac + 4 * j) * 16) = pa[j];
    #pragma unroll
    for (int j = 0; j < 2; j++)
        *(uint4*)(sm + SM_BS + brow * RB + (bc + 8 * j) * 16) = pb[j];
    __syncthreads();

    for (int it = 0; it < NIT; it++) {
        const int cur = it & 1;
        const uint32_t abuf = cur * (128 * RB);
        const uint32_t bbuf = cur * (64 * RB);

        if (it + 1 < NIT) {              // prefetch next slab to registers
            const int ko = (it + 1) * (BKF / 8);
            #pragma unroll
            for (int j = 0; j < 4; j++) pa[j] = ag[ko + ac + 4 * j];
            #pragma unroll
            for (int j = 0; j < 2; j++) pb[j] = bg[ko + bc + 8 * j];
        }

        Frag fr[2];
        #pragma unroll
        for (int mt = 0; mt < 2; mt++)
            ldsm_x4(fr[0].a[mt][0], fr[0].a[mt][1], fr[0].a[mt][2], fr[0].a[mt][3],
                    abase[mt] + abuf);
        ldsm_x4(fr[0].b0[0], fr[0].b0[1], fr[0].b0[2], fr[0].b0[3], b0base + bbuf);
        ldsm_x4(fr[0].b1[0], fr[0].b1[1], fr[0].b1[2], fr[0].b1[3], b1base + bbuf);

        #pragma unroll
        for (int kk = 0; kk < 4; kk++) {          // 4 x k16 = 64 cols per half
            const int cf = kk & 1, nf = cf ^ 1;
            if (kk + 1 < 4) {
                const uint32_t off = (uint32_t)(kk + 1) * 32u;
                #pragma unroll
                for (int mt = 0; mt < 2; mt++)
                    ldsm_x4(fr[nf].a[mt][0], fr[nf].a[mt][1], fr[nf].a[mt][2], fr[nf].a[mt][3],
                            abase[mt] + abuf + off);
                ldsm_x4(fr[nf].b0[0], fr[nf].b0[1], fr[nf].b0[2], fr[nf].b0[3],
                        b0base + bbuf + off);
                ldsm_x4(fr[nf].b1[0], fr[nf].b1[1], fr[nf].b1[2], fr[nf].b1[3],
                        b1base + bbuf + off);
            }
            #pragma unroll
            for (int mt = 0; mt < 2; mt++) {
                mma_bf16(acc[mt][0], fr[cf].a[mt], fr[cf].b0[0], fr[cf].b0[2]);
                mma_bf16(acc[mt][1], fr[cf].a[mt], fr[cf].b0[1], fr[cf].b0[3]);
                mma_bf16(acc[mt][2], fr[cf].a[mt], fr[cf].b1[0], fr[cf].b1[2]);
                mma_bf16(acc[mt][3], fr[cf].a[mt], fr[cf].b1[1], fr[cf].b1[3]);
            }
        }

        if (it + 1 < NIT) {
            const int nxt = cur ^ 1;
            #pragma unroll
            for (int j = 0; j < 4; j++)
                *(uint4*)(sm + SM_AS + (nxt * 128 + arow) * RB + (ac + 4 * j) * 16) = pa[j];
            #pragma unroll
            for (int j = 0; j < 2; j++)
                *(uint4*)(sm + SM_BS + (nxt * 64 + brow) * RB + (bc + 8 * j) * 16) = pb[j];
            __syncthreads();
        }
    }
    __syncthreads();   // all smem reads finished before exchange reuses B area

    // ---- combine split-K halves through smem ----
    float* ex = (float*)(sm + SM_EX);    // [wg][c(32)][lane(32)]
    if (half == 1) {
        #pragma unroll
        for (int mt = 0; mt < 2; mt++)
            #pragma unroll
            for (int nt = 0; nt < 4; nt++)
                #pragma unroll
                for (int k = 0; k < 4; k++)
                    ex[(wg * 32 + (mt * 4 + nt) * 4 + k) * 32 + lane] = acc[mt][nt][k];
    }
    __syncthreads();

    // ---- epilogue (warps 0-7): add, ln, stage; then all warps store ----
    float* stg = (float*)(sm + SM_AS);   // 128 rows x 68 floats = 34816 B
    if (half == 0) {
        #pragma unroll
        for (int mt = 0; mt < 2; mt++)
            #pragma unroll
            for (int nt = 0; nt < 4; nt++)
                #pragma unroll
                for (int k = 0; k < 4; k++)
                    acc[mt][nt][k] += ex[(wg * 32 + (mt * 4 + nt) * 4 + k) * 32 + lane];

        const int g = lane >> 2, t4 = lane & 3;
        #pragma unroll
        for (int mt = 0; mt < 2; mt++) {
            const int r0 = wm * 32 + mt * 16 + g;
            const float mx0 = __ldg(&g_mx[bm + r0]);
            const float mx1 = __ldg(&g_mx[bm + r0 + 8]);
            #pragma unroll
            for (int nt = 0; nt < 4; nt++) {
                const int c0 = wn * 32 + nt * 8 + 2 * t4;
                stg[r0 * 68 + c0]           = mx0 + T_VAL * (fast_ln(acc[mt][nt][0]) - CA_SHIFT);
                stg[r0 * 68 + c0 + 1]       = mx0 + T_VAL * (fast_ln(acc[mt][nt][1]) - CA_SHIFT);
                stg[(r0 + 8) * 68 + c0]     = mx1 + T_VAL * (fast_ln(acc[mt][nt][2]) - CA_SHIFT);
                stg[(r0 + 8) * 68 + c0 + 1] = mx1 + T_VAL * (fast_ln(acc[mt][nt][3]) - CA_SHIFT);
            }
        }
    }
    __syncthreads();

    #pragma unroll
    for (int s = 0; s < 4; s++) {        // 2048 float4 chunks / 512 threads
        const int i = tid + s * 512;
        const int r = i >> 4, c4 = i & 15;
        float4 v = *(float4*)&stg[r * 68 + c4 * 4];
        *(float4*)&out[(size_t)(bm + r) * NDIM + bn + c4 * 4] = v;
    }
}

// ---------------- launch ----------------

extern "C" void kernel_launch(void* const* d_in, const int* in_sizes, int n_in,
                              void* d_out, int out_size)
{
    const float* x = (const float*)d_in[0];
    const float* W = (const float*)d_in[1];
    int nx = in_sizes[0], nw = in_sizes[1];
    if (nx == NDIM * KDIM && nw != NDIM * KDIM) {   // input-order safety
        const float* t = x; x = W; W = t;
        int ts = nx; nx = nw; nw = ts;
    }
    const int B = nx / KDIM;   // 2048

    const int prep_rows = B + NDIM;                   // 2560
    prep_kernel<<<(prep_rows + 7) / 8, 256>>>(x, W, B);

    cudaFuncSetAttribute(lse_gemm_kernel,
                         cudaFuncAttributeMaxDynamicSharedMemorySize, SM_TOT);

    cudaLaunchConfig_t cfg = {};
    cfg.gridDim  = dim3(NDIM / 64, B / 128, 1);       // (8,16) = 128 CTAs
    cfg.blockDim = dim3(512, 1, 1);
    cfg.dynamicSmemBytes = SM_TOT;
    cfg.stream   = 0;
    cudaLaunchAttribute attr[1];
    attr[0].id = cudaLaunchAttributeProgrammaticStreamSerialization;
    attr[0].val.programmaticStreamSerializationAllowed = 1;
    cfg.attrs = attr;
    cfg.numAttrs = 1;
    cudaError_t e = cudaLaunchKernelEx(&cfg, lse_gemm_kernel, (float*)d_out);
    if (e != cudaSuccess) {
        dim3 grid(NDIM / 64, B / 128);
        lse_gemm_kernel<<<grid, 512, SM_TOT>>>((float*)d_out);
    }
}